// round 9
// baseline (speedup 1.0000x reference)
#include <cuda_runtime.h>
#include <cuda_bf16.h>
#include <cuda_fp8.h>
#include <math.h>
#include <stdint.h>

// Problem constants
#define B_DIM 8192
#define D_DIM 1024
#define K_DIM 2048
#define E_DIM 512
#define BETA_F 0.001f

#define WSCALE 32.0f       // weight pre-scale (std 0.03 -> ~1)
#define PSCALE 2048.0f     // softmax-prob pre-scale (1/K -> ~1)

// ---------------------------------------------------------------------------
// Scratch (device globals: allocation-free per harness rules)
// ---------------------------------------------------------------------------
__device__ __align__(256) __nv_bfloat16 g_S_BF[(size_t)B_DIM * K_DIM];   // scaled logits-cross
__device__ __align__(256) float g_REC[(size_t)B_DIM * D_DIM];            // recon fp32
__device__ __align__(256) float g_C2[K_DIM];
__device__ __align__(256) float g_C2B[K_DIM];

__device__ __align__(256) uint8_t g_IMG8[(size_t)B_DIM * D_DIM];   // images e4m3
__device__ __align__(256) uint8_t g_PW8[(size_t)K_DIM * D_DIM];    // 32*project_w (K,D)
__device__ __align__(256) uint8_t g_PWT8[(size_t)D_DIM * K_DIM];   // 32*project_w^T (D,K)
__device__ __align__(256) uint8_t g_RW8[(size_t)E_DIM * K_DIM];    // 32*rec_w (E,K)
__device__ __align__(256) uint8_t g_RWT8[(size_t)K_DIM * E_DIM];   // 32*rec_w^T (K,E)
__device__ __align__(256) uint8_t g_XP8[(size_t)B_DIM * K_DIM];    // 2048*xp / 2048*yp
__device__ __align__(256) uint8_t g_LAT8[(size_t)B_DIM * E_DIM];   // 2048*lat

// ---------------------------------------------------------------------------
// PTX helpers
// ---------------------------------------------------------------------------
__device__ __forceinline__ uint32_t smem_u32(const void* p) {
    return (uint32_t)__cvta_generic_to_shared(p);
}
__device__ __forceinline__ void cp16(void* s, const void* g) {
    uint32_t sa = smem_u32(s);
    asm volatile("cp.async.cg.shared.global [%0], [%1], 16;" :: "r"(sa), "l"(g));
}
__device__ __forceinline__ void ldsm_x4(uint32_t addr, uint32_t& r0, uint32_t& r1,
                                        uint32_t& r2, uint32_t& r3) {
    asm volatile("ldmatrix.sync.aligned.m8n8.x4.shared.b16 {%0,%1,%2,%3}, [%4];"
                 : "=r"(r0), "=r"(r1), "=r"(r2), "=r"(r3) : "r"(addr));
}
// FP8 e4m3 MMA, K=32. Byte-layout of fragments identical to bf16 m16n8k16,
// so the same ldmatrix addressing feeds it.
__device__ __forceinline__ void mma_fp8(float* c, const uint32_t* a, uint32_t b0, uint32_t b1) {
    asm volatile(
        "mma.sync.aligned.m16n8k32.row.col.f32.e4m3.e4m3.f32 "
        "{%0,%1,%2,%3},{%4,%5,%6,%7},{%8,%9},{%0,%1,%2,%3};"
        : "+f"(c[0]), "+f"(c[1]), "+f"(c[2]), "+f"(c[3])
        : "r"(a[0]), "r"(a[1]), "r"(a[2]), "r"(a[3]), "r"(b0), "r"(b1));
}
// pack two fp32 -> e4m3x2 (lo -> low byte)
__device__ __forceinline__ unsigned short fp8x2(float lo, float hi) {
    unsigned short p;
    asm("cvt.rn.satfinite.e4m3x2.f32 %0, %1, %2;" : "=h"(p) : "f"(hi), "f"(lo));
    return p;
}
__device__ __forceinline__ uint32_t fp8x4(float f0, float f1, float f2, float f3) {
    return (uint32_t)fp8x2(f0, f1) | ((uint32_t)fp8x2(f2, f3) << 16);
}

// Byte offset of 16B chunk (r, cc) in a tile with 64B rows (64 fp8 k-elems).
// Swizzle cc ^ ((r>>1)&3): conflict-free ldmatrix phases (validated R5/R7).
__device__ __forceinline__ int tile_off(int r, int cc) {
    return r * 64 + ((cc ^ ((r >> 1) & 3)) * 16);
}

// epilogue store helpers (alpha pre-applied by caller)
__device__ __forceinline__ void store2(float* C, size_t off, float x, float y) {
    *(float2*)(C + off) = make_float2(x, y);
}
__device__ __forceinline__ void store2(__nv_bfloat16* C, size_t off, float x, float y) {
    *(__nv_bfloat162*)(C + off) = __floats2bfloat162_rn(x, y);
}
__device__ __forceinline__ void store2(__nv_fp8_e4m3* C, size_t off, float x, float y) {
    *(unsigned short*)((uint8_t*)C + off) = fp8x2(x, y);
}

// ---------------------------------------------------------------------------
// FP8 NT GEMM: C[M,N] = alpha * A[M,Kd] (row-major e4m3) * B[N,Kd]^T (e4m3)
// CTA tile 128x256x64(fp8), 8 warps (2x4), warp tile 64x64, 4-stage cp.async.
// M % 128 == 0, N % 256 == 0, Kd % 64 == 0.
// ---------------------------------------------------------------------------
#define NSTAGE 4
#define A_BYTES 8192                      // 128 rows x 64B
#define B_BYTES 16384                     // 256 rows x 64B
#define STAGE_BYTES (A_BYTES + B_BYTES)   // 24 KB
#define GEMM_SMEM (NSTAGE * STAGE_BYTES)  // 96 KB

template <typename OutT>
__global__ __launch_bounds__(256, 1)
void gemm_fp8(OutT* __restrict__ C, const uint8_t* __restrict__ A,
              const uint8_t* __restrict__ Bm, int M, int N, int Kd, float alpha) {
    extern __shared__ __align__(16) unsigned char sm[];

    const int t = threadIdx.x;
    const int lane = t & 31;
    const int wid = t >> 5;
    const int wm = wid >> 2;   // 0..1 (64-row half)
    const int wn = wid & 3;    // 0..3 (64-col quarter)
    const int m0 = blockIdx.y * 128;
    const int n0 = blockIdx.x * 256;
    const int nk = Kd >> 6;    // 64 fp8 k-elems per stage

    auto load_tile = [&](int stage, int kt) {
        unsigned char* base = sm + stage * STAGE_BYTES;
#pragma unroll
        for (int i = 0; i < 2; i++) {        // A chunks (512 of 16B)
            int g = t + i * 256;
            int r = g >> 2, cc = g & 3;
            cp16(base + tile_off(r, cc),
                 A + (size_t)(m0 + r) * Kd + kt * 64 + cc * 16);
        }
#pragma unroll
        for (int i = 2; i < 6; i++) {        // B chunks (1024 of 16B)
            int g = t + i * 256;
            int r = (g >> 2) - 128, cc = g & 3;
            cp16(base + A_BYTES + tile_off(r, cc),
                 Bm + (size_t)(n0 + r) * Kd + kt * 64 + cc * 16);
        }
    };

    float acc[4][8][4];
#pragma unroll
    for (int i = 0; i < 4; i++)
#pragma unroll
        for (int j = 0; j < 8; j++)
#pragma unroll
            for (int q = 0; q < 4; q++) acc[i][j][q] = 0.0f;

    // Prologue: fill NSTAGE-1 = 3 stages
#pragma unroll
    for (int s = 0; s < NSTAGE - 1; s++) {
        load_tile(s, s);
        asm volatile("cp.async.commit_group;" ::: "memory");
    }

    for (int kt = 0; kt < nk; kt++) {
        asm volatile("cp.async.wait_group 2;" ::: "memory");
        __syncthreads();

        unsigned char* As = sm + (kt & (NSTAGE - 1)) * STAGE_BYTES;
        unsigned char* Bs = As + A_BYTES;

#pragma unroll
        for (int ks = 0; ks < 2; ks++) {     // 32 fp8 k-elems per ks
            uint32_t a[4][4], b[4][4];
#pragma unroll
            for (int mt = 0; mt < 4; mt++) {
                int rr = wm * 64 + mt * 16 + (lane & 15);
                int ch = ks * 2 + (lane >> 4);
                ldsm_x4(smem_u32(As + tile_off(rr, ch)),
                        a[mt][0], a[mt][1], a[mt][2], a[mt][3]);
            }
#pragma unroll
            for (int g = 0; g < 4; g++) {
                int nr = wn * 64 + g * 16 + ((lane >> 4) & 1) * 8 + (lane & 7);
                int ch = ks * 2 + ((lane >> 3) & 1);
                ldsm_x4(smem_u32(Bs + tile_off(nr, ch)),
                        b[g][0], b[g][1], b[g][2], b[g][3]);
            }
#pragma unroll
            for (int mt = 0; mt < 4; mt++)
#pragma unroll
                for (int nt = 0; nt < 8; nt++) {
                    uint32_t b0 = b[nt >> 1][(nt & 1) * 2];
                    uint32_t b1 = b[nt >> 1][(nt & 1) * 2 + 1];
                    mma_fp8(acc[mt][nt], a[mt], b0, b1);
                }
        }

        const int nxt = kt + NSTAGE - 1;
        if (nxt < nk) {
            load_tile(nxt & (NSTAGE - 1), nxt);
        }
        asm volatile("cp.async.commit_group;" ::: "memory");
    }

    // Epilogue (alpha applied here)
#pragma unroll
    for (int mt = 0; mt < 4; mt++) {
        int row = m0 + wm * 64 + mt * 16 + (lane >> 2);
#pragma unroll
        for (int nt = 0; nt < 8; nt++) {
            int col = n0 + wn * 64 + nt * 8 + (lane & 3) * 2;
            store2(C, (size_t)row * N + col,
                   alpha * acc[mt][nt][0], alpha * acc[mt][nt][1]);
            store2(C, (size_t)(row + 8) * N + col,
                   alpha * acc[mt][nt][2], alpha * acc[mt][nt][3]);
        }
    }
}

// ---------------------------------------------------------------------------
// Conversion / transpose kernels (fp32 -> scaled e4m3)
// ---------------------------------------------------------------------------
__global__ void conv_fp8_kernel(const float* __restrict__ in, uint8_t* __restrict__ out,
                                int n8, float scale) {
    int i = blockIdx.x * blockDim.x + threadIdx.x;
    if (i < n8) {
        float4 v0 = ((const float4*)in)[2 * i];
        float4 v1 = ((const float4*)in)[2 * i + 1];
        uint2 o;
        o.x = fp8x4(scale * v0.x, scale * v0.y, scale * v0.z, scale * v0.w);
        o.y = fp8x4(scale * v1.x, scale * v1.y, scale * v1.z, scale * v1.w);
        ((uint2*)out)[i] = o;
    }
}

// out (C x R) e4m3 = scale * transpose of in (R x C) fp32. R, C multiples of 32.
__global__ void transpose_fp8_kernel(const float* __restrict__ in,
                                     uint8_t* __restrict__ out, int R, int C, float scale) {
    __shared__ float tile[32][33];
    int x = blockIdx.x * 32 + threadIdx.x;
    int y0 = blockIdx.y * 32;
#pragma unroll
    for (int j = 0; j < 32; j += 8)
        tile[threadIdx.y + j][threadIdx.x] = in[(size_t)(y0 + threadIdx.y + j) * C + x];
    __syncthreads();
    int xo = blockIdx.y * 32 + threadIdx.x;
    int yo0 = blockIdx.x * 32;
#pragma unroll
    for (int j = 0; j < 32; j += 8) {
        unsigned short p = fp8x2(scale * tile[threadIdx.x][threadIdx.y + j], 0.0f);
        out[(size_t)(yo0 + threadIdx.y + j) * R + xo] = (uint8_t)(p & 0xFF);
    }
}

// ---------------------------------------------------------------------------
// Row softmax over K=2048 cols (bf16 in / scaled-e4m3 out).
// logit = a*S[row,k] - BETA*c2[k]; out = PSCALE * softmax(logit).
// ---------------------------------------------------------------------------
__global__ void softmax_kernel(const __nv_bfloat16* __restrict__ S,
                               uint8_t* __restrict__ O,
                               const float* __restrict__ c2, float a) {
    const int row = blockIdx.x;
    const int t = threadIdx.x;
    const int lane = t & 31, wid = t >> 5;
    __shared__ float wred[8];

    uint4 v = ((const uint4*)(S + (size_t)row * K_DIM))[t];
    float f[8];
    {
        __nv_bfloat162 h;
        h = *(__nv_bfloat162*)&v.x; f[0] = __low2float(h); f[1] = __high2float(h);
        h = *(__nv_bfloat162*)&v.y; f[2] = __low2float(h); f[3] = __high2float(h);
        h = *(__nv_bfloat162*)&v.z; f[4] = __low2float(h); f[5] = __high2float(h);
        h = *(__nv_bfloat162*)&v.w; f[6] = __low2float(h); f[7] = __high2float(h);
    }
    const float4 c0 = *(const float4*)(c2 + t * 8);
    const float4 c1 = *(const float4*)(c2 + t * 8 + 4);
    f[0] = fmaf(a, f[0], -BETA_F * c0.x); f[1] = fmaf(a, f[1], -BETA_F * c0.y);
    f[2] = fmaf(a, f[2], -BETA_F * c0.z); f[3] = fmaf(a, f[3], -BETA_F * c0.w);
    f[4] = fmaf(a, f[4], -BETA_F * c1.x); f[5] = fmaf(a, f[5], -BETA_F * c1.y);
    f[6] = fmaf(a, f[6], -BETA_F * c1.z); f[7] = fmaf(a, f[7], -BETA_F * c1.w);

    float mx = f[0];
#pragma unroll
    for (int i = 1; i < 8; i++) mx = fmaxf(mx, f[i]);
#pragma unroll
    for (int off = 16; off; off >>= 1) mx = fmaxf(mx, __shfl_xor_sync(0xffffffffu, mx, off));
    if (lane == 0) wred[wid] = mx;
    __syncthreads();
    float m = wred[0];
#pragma unroll
    for (int w = 1; w < 8; w++) m = fmaxf(m, wred[w]);
    __syncthreads();

    float sum = 0.0f;
#pragma unroll
    for (int i = 0; i < 8; i++) {
        f[i] = expf(f[i] - m);
        sum += f[i];
    }
#pragma unroll
    for (int off = 16; off; off >>= 1) sum += __shfl_xor_sync(0xffffffffu, sum, off);
    if (lane == 0) wred[wid] = sum;
    __syncthreads();
    float tot = wred[0];
#pragma unroll
    for (int w = 1; w < 8; w++) tot += wred[w];
    const float inv = PSCALE / tot;

    uint2 o;
    o.x = fp8x4(f[0] * inv, f[1] * inv, f[2] * inv, f[3] * inv);
    o.y = fp8x4(f[4] * inv, f[5] * inv, f[6] * inv, f[7] * inv);
    ((uint2*)(O + (size_t)row * K_DIM))[t] = o;
}

// ---------------------------------------------------------------------------
// Norm precomputes + loss (exact fp32 path)
// ---------------------------------------------------------------------------
__device__ __forceinline__ float block_sum256(float v, float* red) {
    int t = threadIdx.x;
    red[t] = v;
    __syncthreads();
#pragma unroll
    for (int s = 128; s > 0; s >>= 1) {
        if (t < s) red[t] += red[t + s];
        __syncthreads();
    }
    float r = red[0];
    __syncthreads();
    return r;
}

__global__ void rowmeansq_kernel(const float* __restrict__ W, float* __restrict__ out, int cols) {
    __shared__ float red[256];
    const int row = blockIdx.x, t = threadIdx.x;
    const float* w = W + (size_t)row * cols;
    float s = 0.0f;
    for (int c = t; c < cols; c += 256) { float v = w[c]; s += v * v; }
    s = block_sum256(s, red);
    if (t == 0) out[row] = s / (float)cols;
}

__global__ void colmeansq_kernel(const float* __restrict__ W, float* __restrict__ out,
                                 int rows, int cols) {
    int k = blockIdx.x * blockDim.x + threadIdx.x;
    if (k < cols) {
        float s = 0.0f;
        for (int e = 0; e < rows; e++) { float v = W[(size_t)e * cols + k]; s += v * v; }
        out[k] = s / (float)rows;
    }
}

__global__ void loss_kernel(const float* __restrict__ recon, const float* __restrict__ img,
                            float* __restrict__ out, int cols) {
    __shared__ float red[256];
    const int row = blockIdx.x, t = threadIdx.x;
    const float* rr = recon + (size_t)row * cols;
    const float* x = img + (size_t)row * cols;
    float s = 0.0f;
    for (int c = t; c < cols; c += 256) { float d = rr[c] - x[c]; s += d * d; }
    s = block_sum256(s, red);
    if (t == 0) out[row] = s / (float)cols;
}

// ---------------------------------------------------------------------------
// Launch
// ---------------------------------------------------------------------------
extern "C" void kernel_launch(void* const* d_in, const int* in_sizes, int n_in,
                              void* d_out, int out_size) {
    const float* images    = (const float*)d_in[0];   // (B, D)
    const float* project_w = (const float*)d_in[1];   // (K, D)
    const float* rec_w     = (const float*)d_in[2];   // (E, K)
    float* loss_out        = (float*)d_out;           // (B,)

    float *REC, *C2, *C2B;
    __nv_bfloat16* S;
    uint8_t *IMG8, *PW8, *PWT8, *RW8, *RWT8, *XP8, *LAT8;
    cudaGetSymbolAddress((void**)&S,    g_S_BF);
    cudaGetSymbolAddress((void**)&REC,  g_REC);
    cudaGetSymbolAddress((void**)&C2,   g_C2);
    cudaGetSymbolAddress((void**)&C2B,  g_C2B);
    cudaGetSymbolAddress((void**)&IMG8, g_IMG8);
    cudaGetSymbolAddress((void**)&PW8,  g_PW8);
    cudaGetSymbolAddress((void**)&PWT8, g_PWT8);
    cudaGetSymbolAddress((void**)&RW8,  g_RW8);
    cudaGetSymbolAddress((void**)&RWT8, g_RWT8);
    cudaGetSymbolAddress((void**)&XP8,  g_XP8);
    cudaGetSymbolAddress((void**)&LAT8, g_LAT8);

    cudaFuncSetAttribute(gemm_fp8<__nv_bfloat16>,
                         cudaFuncAttributeMaxDynamicSharedMemorySize, GEMM_SMEM);
    cudaFuncSetAttribute(gemm_fp8<__nv_fp8_e4m3>,
                         cudaFuncAttributeMaxDynamicSharedMemorySize, GEMM_SMEM);
    cudaFuncSetAttribute(gemm_fp8<float>,
                         cudaFuncAttributeMaxDynamicSharedMemorySize, GEMM_SMEM);

    // fp8 conversions + transposes (weights pre-scaled by WSCALE)
    {
        int n8 = (B_DIM * D_DIM) / 8;
        conv_fp8_kernel<<<(n8 + 255) / 256, 256>>>(images, IMG8, n8, 1.0f);
        n8 = (K_DIM * D_DIM) / 8;
        conv_fp8_kernel<<<(n8 + 255) / 256, 256>>>(project_w, PW8, n8, WSCALE);
        n8 = (E_DIM * K_DIM) / 8;
        conv_fp8_kernel<<<(n8 + 255) / 256, 256>>>(rec_w, RW8, n8, WSCALE);
        transpose_fp8_kernel<<<dim3(D_DIM / 32, K_DIM / 32), dim3(32, 8)>>>(
            project_w, PWT8, K_DIM, D_DIM, WSCALE);
        transpose_fp8_kernel<<<dim3(K_DIM / 32, E_DIM / 32), dim3(32, 8)>>>(
            rec_w, RWT8, E_DIM, K_DIM, WSCALE);
    }

    // Column-norm precomputes (exact fp32)
    rowmeansq_kernel<<<K_DIM, 256>>>(project_w, C2, D_DIM);
    colmeansq_kernel<<<K_DIM / 256, 256>>>(rec_w, C2B, E_DIM, K_DIM);

    // G1: S = WSCALE * (images @ project_w^T)  (B x K)
    gemm_fp8<__nv_bfloat16><<<dim3(K_DIM / 256, B_DIM / 128), 256, GEMM_SMEM>>>(
        S, IMG8, PW8, B_DIM, K_DIM, D_DIM, 1.0f);

    // softmax1 -> xp (fp8, xPSCALE); logit scale folds out WSCALE
    softmax_kernel<<<B_DIM, 256>>>(S, XP8, C2, BETA_F * 2.0f / (float)D_DIM / WSCALE);

    // G2: LAT8 = PSCALE * lat = (XP8 @ RW8^T) / WSCALE   (B x E)
    gemm_fp8<__nv_fp8_e4m3><<<dim3(E_DIM / 256, B_DIM / 128), 256, GEMM_SMEM>>>(
        (__nv_fp8_e4m3*)LAT8, XP8, RW8, B_DIM, E_DIM, K_DIM, 1.0f / WSCALE);

    // G3: S = PSCALE*WSCALE * (lat @ rec_w)  (B x K)
    gemm_fp8<__nv_bfloat16><<<dim3(K_DIM / 256, B_DIM / 128), 256, GEMM_SMEM>>>(
        S, LAT8, RWT8, B_DIM, K_DIM, E_DIM, 1.0f);

    // softmax2 -> yp (fp8, xPSCALE); logit scale folds out PSCALE*WSCALE
    softmax_kernel<<<B_DIM, 256>>>(S, XP8, C2B,
                                   BETA_F * 2.0f / (float)E_DIM / (WSCALE * PSCALE));

    // G4: REC = (yp @ project_w) = (XP8 @ PWT8^T) / (PSCALE*WSCALE)  (B x D)
    gemm_fp8<float><<<dim3(D_DIM / 256, B_DIM / 128), 256, GEMM_SMEM>>>(
        REC, XP8, PWT8, B_DIM, D_DIM, K_DIM, 1.0f / (WSCALE * PSCALE));

    // loss (exact fp32)
    loss_kernel<<<B_DIM, 256>>>(REC, images, loss_out, D_DIM);
}